// round 14
// baseline (speedup 1.0000x reference)
#include <cuda_runtime.h>
#include <cuda_bf16.h>
#include <cuda_fp16.h>
#include <cstdint>

// ---------------------------------------------------------------------------
// LSTM with attention-weighted inputs.  B=256, SEQ=128, IN=H=512.
// Gate dim PERMUTED: column n = 4*k + gate.
// SINGLE PERSISTENT KERNEL (512 CTAs, all co-resident, grid spin-barrier):
//   G1 (cta 0..255):  phase A attention(batch)   | phase B xi-GEMM + update
//   G2 (cta 256..511): phase A h-half GEMM        | phase B idle
// W slabs live in smem for ALL 128 steps (loaded once). A tiles stream via
// cp.async.bulk rings. (tcgen05 unavailable: harness PTX target is sm_103.)
// ---------------------------------------------------------------------------

#define BATCH 256
#define SEQ   128
#define IN    512
#define H     512
#define NG    2048
#define ATILE 8192                 // 64 rows x 128B (K=64 fp16)
#define BTILE 4096                 // 32 rows x 128B
#define DSM   49152                // W 32K resident + 16K ring/attn scratch

__device__ unsigned char g_AT[4 * 16 * ATILE];     // [mblk][ktile] fp16
__device__ unsigned char g_WT[64 * 16 * BTILE];    // [nblk][ktile] fp16
__device__ float         g_bias[NG];
__device__ __half2       g_x16 [BATCH * SEQ * (IN/2)];
__device__ __half2       g_Wa16[SEQ * (IN/2)];
__device__ float         g_c   [BATCH * H];
__device__ float         g_gates[BATCH * NG];      // h-half partial (+bias)
__device__ unsigned      g_bar_count;
__device__ unsigned      g_bar_gen;

__device__ __forceinline__ uint32_t swz(uint32_t o) { return o ^ ((o >> 3) & 0x70u); }
__device__ __forceinline__ float sigf(float x) { return 1.0f / (1.0f + expf(-x)); }

__device__ __forceinline__ uint32_t smem_u32(const void* p) {
    uint32_t a;
    asm("{ .reg .u64 t; cvta.to.shared.u64 t, %1; cvt.u32.u64 %0, t; }" : "=r"(a) : "l"(p));
    return a;
}
#define FENCE_PROXY_ASYNC asm volatile("fence.proxy.async;" ::: "memory")
#define MBAR_INIT(a, n) asm volatile("mbarrier.init.shared.b64 [%0], %1;" :: "r"(a), "r"(n) : "memory")
#define MBAR_EXPECT_TX(a, b) asm volatile("mbarrier.arrive.expect_tx.shared.b64 _, [%0], %1;" :: "r"(a), "r"(b) : "memory")
#define MBAR_WAIT(a, par) do { \
    asm volatile("{ .reg .pred P; WL%=: mbarrier.try_wait.parity.acquire.cta.shared::cta.b64 P, [%0], %1, 0x989680; @P bra.uni WD%=; bra.uni WL%=; WD%=: }" \
                 :: "r"(a), "r"(par) : "memory"); } while (0)

__device__ __forceinline__ void bulk_g2s(uint32_t dst, const void* src, uint32_t bytes, uint32_t mbar) {
    asm volatile("cp.async.bulk.shared::cluster.global.mbarrier::complete_tx::bytes [%0], [%1], %2, [%3];"
                 :: "r"(dst), "l"(src), "r"(bytes), "r"(mbar) : "memory");
}

__device__ __forceinline__ void ldm_x4(uint32_t* r, const void* p) {
    uint32_t a = smem_u32(p);
    asm volatile("ldmatrix.sync.aligned.m8n8.x4.shared.b16 {%0,%1,%2,%3}, [%4];"
                 : "=r"(r[0]), "=r"(r[1]), "=r"(r[2]), "=r"(r[3]) : "r"(a));
}
__device__ __forceinline__ void mma16816(float* c, const uint32_t* a, uint32_t b0, uint32_t b1) {
    asm volatile(
        "mma.sync.aligned.m16n8k16.row.col.f32.f16.f16.f32 "
        "{%0,%1,%2,%3}, {%4,%5,%6,%7}, {%8,%9}, {%0,%1,%2,%3};"
        : "+f"(c[0]), "+f"(c[1]), "+f"(c[2]), "+f"(c[3])
        : "r"(a[0]), "r"(a[1]), "r"(a[2]), "r"(a[3]), "r"(b0), "r"(b1));
}

// grid-wide sense barrier (gen monotonic -> graph-replay safe)
__device__ __forceinline__ void grid_barrier() {
    __syncthreads();
    if (threadIdx.x == 0) {
        unsigned mygen = *(volatile unsigned*)&g_bar_gen;
        __threadfence();
        unsigned old = atomicAdd(&g_bar_count, 1);
        if (old == gridDim.x - 1) {
            atomicExch(&g_bar_count, 0);
            __threadfence();
            atomicAdd(&g_bar_gen, 1);
        } else {
            while (*(volatile unsigned*)&g_bar_gen == mygen) __nanosleep(64);
        }
        __threadfence();
    }
    __syncthreads();
}

// 32m x 16n over 2 kq (K=32): 3 LDSM.x4, 4 mma
__device__ __forceinline__ void c3216(const unsigned char* A, const unsigned char* B,
                                      int wm, int wn, int lane, int kq0, float acc[2][2][4]) {
    #pragma unroll
    for (int q = 0; q < 2; q++) {
        const int kb = (kq0 + q) * 16;
        uint32_t a0[4], a1[4], b0[4];
        const uint32_t kcol = (kb + (lane >> 4) * 8) * 2;
        ldm_x4(a0, A + swz((wm + (lane & 15)) * 128 + kcol));
        ldm_x4(a1, A + swz((wm + 16 + (lane & 15)) * 128 + kcol));
        const int br = wn + (lane & 7) + ((lane >> 4) << 3);
        ldm_x4(b0, B + swz(br * 128 + (kb + ((lane >> 3) & 1) * 8) * 2));
        mma16816(acc[0][0], a0, b0[0], b0[1]);
        mma16816(acc[0][1], a0, b0[2], b0[3]);
        mma16816(acc[1][0], a1, b0[0], b0[1]);
        mma16816(acc[1][1], a1, b0[2], b0[3]);
    }
}

// ---------------- prep ---------------------------------------------------------
__global__ void prep_a(const float* __restrict__ W_ih, const float* __restrict__ W_hh,
                       const float* __restrict__ b_ih, const float* __restrict__ b_hh) {
    int i = blockIdx.x * blockDim.x + threadIdx.x;
    int n = i >> 10, kc = i & 1023;
    int j = (n & 3) * 512 + (n >> 2);
    float w = (kc < IN) ? W_ih[j * IN + kc] : W_hh[j * H + (kc - IN)];
    uint32_t off = (uint32_t)((n >> 5) * 16 + (kc >> 6)) * BTILE + swz((n & 31) * 128 + (kc & 63) * 2);
    *(__half*)(g_WT + off) = __float2half_rn(w);
    if (i < NG) {
        int jb = (i & 3) * 512 + (i >> 2);
        g_bias[i] = b_ih[jb] + b_hh[jb];
    }
}

__global__ void prep_b(const float* __restrict__ x, const float* __restrict__ Wa) {
    int blk = blockIdx.x, tid = threadIdx.x;
    if (blk < 8192) {
        size_t i = (size_t)blk * 1024 + tid;
        float2 v = ((const float2*)x)[i];
        g_x16[i] = __floats2half2_rn(v.x, v.y);
    } else if (blk < 8224) {
        int i = (blk - 8192) * 1024 + tid;
        float2 v = ((const float2*)Wa)[i];
        g_Wa16[i] = __floats2half2_rn(v.x, v.y);
    } else {
        int b = (blk - 8224) * 2 + (tid >> 9);
        int k = tid & 511;
        float gi = g_bias[k * 4 + 0], gg = g_bias[k * 4 + 2], go = g_bias[k * 4 + 3];
        float c0 = sigf(gi) * tanhf(gg);
        float h0 = sigf(go) * tanhf(c0);
        g_c[b * H + k] = c0;
        uint32_t off = (uint32_t)((b >> 6) * 16 + 8 + (k >> 6)) * ATILE + swz((b & 63) * 128 + (k & 63) * 2);
        *(__half*)(g_AT + off) = __float2half_rn(h0);
    }
}

// ---------------- attention body (256 thr, 1 batch) ---------------------------
struct AttnS {
    float c_sm[IN];
    float logit[SEQ], attn[SEQ];
    float rmax[4], rsum[4];
    float xpart[4][IN];
};

__device__ __forceinline__ void attn_body(unsigned char* dyn, int b, const float* __restrict__ ba) {
    AttnS* s = (AttnS*)dyn;
    const int tid = threadIdx.x, lane = tid & 31, warp = tid >> 5;

    s->c_sm[tid]       = g_c[b * H + tid];
    s->c_sm[256 + tid] = g_c[b * H + 256 + tid];
    __syncthreads();

    float4 cf[4];
    #pragma unroll
    for (int j = 0; j < 4; j++) cf[j] = ((const float4*)s->c_sm)[j * 32 + lane];

    const uint2* wa = (const uint2*)g_Wa16;
    #pragma unroll 2
    for (int si = 0; si < 16; si++) {
        const int sq = warp * 16 + si;
        const uint2* wp = wa + sq * 128;
        float acc = 0.0f;
        #pragma unroll
        for (int j = 0; j < 4; j++) {
            uint2 v = wp[j * 32 + lane];
            float2 w0 = __half22float2(*(const __half2*)&v.x);
            float2 w1 = __half22float2(*(const __half2*)&v.y);
            acc += cf[j].x * w0.x + cf[j].y * w0.y + cf[j].z * w1.x + cf[j].w * w1.y;
        }
        #pragma unroll
        for (int off = 16; off > 0; off >>= 1) acc += __shfl_xor_sync(0xffffffffu, acc, off);
        if (lane == 0) s->logit[sq] = acc + ba[sq];
    }
    __syncthreads();

    if (tid < 128) {
        float l = s->logit[tid], m = l;
        #pragma unroll
        for (int off = 16; off > 0; off >>= 1) m = fmaxf(m, __shfl_xor_sync(0xffffffffu, m, off));
        if (lane == 0) s->rmax[tid >> 5] = m;
    }
    __syncthreads();
    if (tid < 128) {
        float m = fmaxf(fmaxf(s->rmax[0], s->rmax[1]), fmaxf(s->rmax[2], s->rmax[3]));
        float e = expf(s->logit[tid] - m);
        s->attn[tid] = e;
        #pragma unroll
        for (int off = 16; off > 0; off >>= 1) e += __shfl_xor_sync(0xffffffffu, e, off);
        if (lane == 0) s->rsum[tid >> 5] = e;
    }
    __syncthreads();
    const float inv = 1.0f / (s->rsum[0] + s->rsum[1] + s->rsum[2] + s->rsum[3]);

    {
        const int g = tid >> 6, cth = tid & 63;
        const uint4* xp = ((const uint4*)g_x16) + (size_t)b * SEQ * 64 + cth;
        float acc[8] = {};
        #pragma unroll 4
        for (int i = 0; i < 32; i++) {
            const int sq = g * 32 + i;
            const float a = s->attn[sq];
            uint4 v = xp[(size_t)sq * 64];
            float2 p0 = __half22float2(*(const __half2*)&v.x);
            float2 p1 = __half22float2(*(const __half2*)&v.y);
            float2 p2 = __half22float2(*(const __half2*)&v.z);
            float2 p3 = __half22float2(*(const __half2*)&v.w);
            acc[0] += a * p0.x; acc[1] += a * p0.y;
            acc[2] += a * p1.x; acc[3] += a * p1.y;
            acc[4] += a * p2.x; acc[5] += a * p2.y;
            acc[6] += a * p3.x; acc[7] += a * p3.y;
        }
        #pragma unroll
        for (int q = 0; q < 8; q++) s->xpart[g][cth * 8 + q] = acc[q];
    }
    __syncthreads();

    {
        const int d0 = tid * 2;
        float v0 = (s->xpart[0][d0]     + s->xpart[1][d0])     + (s->xpart[2][d0]     + s->xpart[3][d0]);
        float v1 = (s->xpart[0][d0 + 1] + s->xpart[1][d0 + 1]) + (s->xpart[2][d0 + 1] + s->xpart[3][d0 + 1]);
        v0 *= inv; v1 *= inv;
        uint32_t off = ((uint32_t)(b >> 6) * 16 + (d0 >> 6)) * ATILE + swz((b & 63) * 128 + (d0 & 63) * 2);
        *(__half2*)(g_AT + off) = __floats2half2_rn(v0, v1);
    }
}

// ---------------- persistent main kernel ---------------------------------------
__global__ void __launch_bounds__(256, 4) kmain(float* __restrict__ out,
                                                const float* __restrict__ ba) {
    extern __shared__ unsigned char sm[];
    __shared__ __align__(8) uint64_t wbar, abar[2];

    const int tid = threadIdx.x, lane = tid & 31, warp = tid >> 5;
    const int cta = blockIdx.x;
    const bool g1 = cta < 256;
    const int id = g1 ? cta : cta - 256;
    const int bm = id >> 6, bn = id & 63;
    const int wk = warp & 1, wm = ((warp >> 1) & 1) * 32, wn = (warp >> 2) * 16;

    if (tid == 0) {
        MBAR_INIT(smem_u32(&wbar), 1);
        MBAR_INIT(smem_u32(&abar[0]), 1);
        MBAR_INIT(smem_u32(&abar[1]), 1);
    }
    __syncthreads();

    // resident W slab: G1 -> xi ktiles 0..7, G2 -> h ktiles 8..15 (once, 32KB)
    if (tid == 0) {
        MBAR_EXPECT_TX(smem_u32(&wbar), 32768);
        bulk_g2s(smem_u32(sm), g_WT + (size_t)(bn * 16 + (g1 ? 0 : 8)) * BTILE, 32768,
                 smem_u32(&wbar));
    }
    MBAR_WAIT(smem_u32(&wbar), 0);
    __syncthreads();

    const uint32_t smA = smem_u32(sm) + 32768;
    unsigned acnt[2] = {0, 0};

    for (int t = 0; t < SEQ; t++) {
        // ================= phase A =================
        if (g1) {
            attn_body(sm + 32768, cta, ba);             // writes xi tiles (gmem)
            FENCE_PROXY_ASYNC;                          // visible to phase-B TMA
        } else {
            // h-half GEMM -> g_gates (+bias)
            const unsigned char* Ag = g_AT + (size_t)(bm * 16 + 8) * ATILE;
            if (tid == 0) {
                MBAR_EXPECT_TX(smem_u32(&abar[0]), 8192);
                bulk_g2s(smA, Ag, 8192, smem_u32(&abar[0]));
                MBAR_EXPECT_TX(smem_u32(&abar[1]), 8192);
                bulk_g2s(smA + 8192, Ag + ATILE, 8192, smem_u32(&abar[1]));
            }
            float acc[2][2][4] = {};
            for (int s = 0; s < 8; s++) {
                MBAR_WAIT(smem_u32(&abar[s & 1]), acnt[s & 1] & 1);
                acnt[s & 1]++;
                c3216(sm + 32768 + (s & 1) * 8192, sm + s * BTILE, wm, wn, lane, wk * 2, acc);
                __syncthreads();
                if (tid == 0 && s + 2 < 8) {
                    MBAR_EXPECT_TX(smem_u32(&abar[s & 1]), 8192);
                    bulk_g2s(smA + (s & 1) * 8192, Ag + (size_t)(s + 2) * ATILE, 8192,
                             smem_u32(&abar[s & 1]));
                }
            }
            // reduce 2-way K-split in smem, add bias, store partial gates
            float* gsm = (float*)(sm + 32768);          // [64][36]
            if (wk) {
                #pragma unroll
                for (int mi = 0; mi < 2; mi++)
                    #pragma unroll
                    for (int ni = 0; ni < 2; ni++) {
                        const int r = wm + mi * 16 + (lane >> 2);
                        const int c = wn + ni * 8 + (lane & 3) * 2;
                        gsm[r * 36 + c]           = acc[mi][ni][0];
                        gsm[r * 36 + c + 1]       = acc[mi][ni][1];
                        gsm[(r + 8) * 36 + c]     = acc[mi][ni][2];
                        gsm[(r + 8) * 36 + c + 1] = acc[mi][ni][3];
                    }
            }
            __syncthreads();
            if (!wk) {
                #pragma unroll
                for (int mi = 0; mi < 2; mi++)
                    #pragma unroll
                    for (int ni = 0; ni < 2; ni++) {
                        const int r = wm + mi * 16 + (lane >> 2);
                        const int c = wn + ni * 8 + (lane & 3) * 2;
                        gsm[r * 36 + c]           += acc[mi][ni][0];
                        gsm[r * 36 + c + 1]       += acc[mi][ni][1];
                        gsm[(r + 8) * 36 + c]     += acc[mi][ni][2];
                        gsm[(r + 8) * 36 + c + 1] += acc[mi][ni][3];
                    }
            }
            __syncthreads();
            const int kl = tid & 7;
            const float4 bias = *(const float4*)&g_bias[bn * 32 + kl * 4];
            #pragma unroll
            for (int j = 0; j < 2; j++) {
                const int bl = (tid >> 3) + j * 32;
                float4 v = *(const float4*)&gsm[bl * 36 + kl * 4];
                v.x += bias.x; v.y += bias.y; v.z += bias.z; v.w += bias.w;
                *(float4*)&g_gates[(size_t)(bm * 64 + bl) * NG + bn * 32 + kl * 4] = v;
            }
        }
        grid_barrier();

        // ================= phase B =================
        if (g1) {
            // epilogue operands ready now
            const int kl = tid & 7;
            const int k  = bn * 8 + kl;
            const int bl0 = tid >> 3, bl1 = bl0 + 32;
            const int batch0 = bm * 64 + bl0, batch1 = bm * 64 + bl1;
            const float4 gp0 = *(const float4*)&g_gates[(size_t)batch0 * NG + bn * 32 + kl * 4];
            const float4 gp1 = *(const float4*)&g_gates[(size_t)batch1 * NG + bn * 32 + kl * 4];
            const float cold0 = g_c[batch0 * H + k];
            const float cold1 = g_c[batch1 * H + k];

            const unsigned char* Ag = g_AT + (size_t)(bm * 16) * ATILE;
            if (tid == 0) {
                MBAR_EXPECT_TX(smem_u32(&abar[0]), 8192);
                bulk_g2s(smA, Ag, 8192, smem_u32(&abar[0]));
                MBAR_EXPECT_TX(smem_u32(&abar[1]), 8192);
                bulk_g2s(smA + 8192, Ag + ATILE, 8192, smem_u32(&abar[1]));
            }
            float acc[2][2][4] = {};
            for (int s = 0; s < 8; s++) {
                MBAR_WAIT(smem_u32(&abar[s & 1]), acnt[s & 1] & 1);
                acnt[s & 1]++;
                c3216(sm + 32768 + (s & 1) * 8192, sm + s * BTILE, wm, wn, lane, wk * 2, acc);
                __syncthreads();
                if (tid == 0 && s + 2 < 8) {
                    MBAR_EXPECT_TX(smem_u32(&abar[s & 1]), 8192);
                    bulk_g2s(smA + (s & 1) * 8192, Ag + (size_t)(s + 2) * ATILE, 8192,
                             smem_u32(&abar[s & 1]));
                }
            }
            float* gsm = (float*)(sm + 32768);          // [64][36]
            if (wk) {
                #pragma unroll
                for (int mi = 0; mi < 2; mi++)
                    #pragma unroll
                    for (int ni = 0; ni < 2; ni++) {
                        const int r = wm + mi * 16 + (lane >> 2);
                        const int c = wn + ni * 8 + (lane & 3) * 2;
                        gsm[r * 36 + c]           = acc[mi][ni][0];
                        gsm[r * 36 + c + 1]       = acc[mi][ni][1];
                        gsm[(r + 8) * 36 + c]     = acc[mi][ni][2];
                        gsm[(r + 8) * 36 + c + 1] = acc[mi][ni][3];
                    }
            }
            __syncthreads();
            if (!wk) {
                #pragma unroll
                for (int mi = 0; mi < 2; mi++)
                    #pragma unroll
                    for (int ni = 0; ni < 2; ni++) {
                        const int r = wm + mi * 16 + (lane >> 2);
                        const int c = wn + ni * 8 + (lane & 3) * 2;
                        gsm[r * 36 + c]           += acc[mi][ni][0];
                        gsm[r * 36 + c + 1]       += acc[mi][ni][1];
                        gsm[(r + 8) * 36 + c]     += acc[mi][ni][2];
                        gsm[(r + 8) * 36 + c + 1] += acc[mi][ni][3];
                    }
            }
            __syncthreads();

            const uint32_t tbase = ((uint32_t)bm * 16 + 8 + (k >> 6)) * ATILE;
            {
                float4 s4 = *(const float4*)&gsm[bl0 * 36 + kl * 4];
                float gi = s4.x + gp0.x, gf = s4.y + gp0.y, gg = s4.z + gp0.z, go = s4.w + gp0.w;
                float cn = sigf(gf) * cold0 + sigf(gi) * tanhf(gg);
                float h  = sigf(go) * tanhf(cn);
                g_c[batch0 * H + k] = cn;
                *(__half*)(g_AT + tbase + swz(bl0 * 128 + (k & 63) * 2)) = __float2half_rn(h);
                out[((size_t)batch0 * SEQ + t) * H + k] = h;
            }
            {
                float4 s4 = *(const float4*)&gsm[bl1 * 36 + kl * 4];
                float gi = s4.x + gp1.x, gf = s4.y + gp1.y, gg = s4.z + gp1.z, go = s4.w + gp1.w;
                float cn = sigf(gf) * cold1 + sigf(gi) * tanhf(gg);
                float h  = sigf(go) * tanhf(cn);
                g_c[batch1 * H + k] = cn;
                *(__half*)(g_AT + tbase + swz(bl1 * 128 + (k & 63) * 2)) = __float2half_rn(h);
                out[((size_t)batch1 * SEQ + t) * H + k] = h;
            }
            FENCE_PROXY_ASYNC;                          // h tiles -> next step TMA
        }
        grid_barrier();
    }
}

// ---------------- launcher -------------------------------------------------------
extern "C" void kernel_launch(void* const* d_in, const int* in_sizes, int n_in,
                              void* d_out, int out_size) {
    const float* x    = (const float*)d_in[0];
    const float* W_ih = (const float*)d_in[1];
    const float* W_hh = (const float*)d_in[2];
    const float* b_ih = (const float*)d_in[3];
    const float* b_hh = (const float*)d_in[4];
    const float* Wa   = (const float*)d_in[5];
    const float* ba   = (const float*)d_in[6];
    float* out = (float*)d_out;

    cudaFuncSetAttribute(kmain, cudaFuncAttributeMaxDynamicSharedMemorySize, DSM);

    prep_a<<<2048, 1024>>>(W_ih, W_hh, b_ih, b_hh);
    prep_b<<<8352, 1024>>>(x, Wa);
    kmain<<<512, 256, DSM>>>(out, ba);
}

// round 15
// speedup vs baseline: 1.1666x; 1.1666x over previous
#include <cuda_runtime.h>
#include <cuda_bf16.h>
#include <cuda_fp16.h>
#include <cstdint>

// ---------------------------------------------------------------------------
// LSTM with attention-weighted inputs.  B=256, SEQ=128, IN=H=512.
// Gate dim PERMUTED: column n = 4*k + gate.
// A=[xi|h] fp16 tiles; W fp16 tiles, pre-swizzled (SW128) in gmem.
// PDL pipeline per step, with a fine-grained xi handshake:
//   k1: blocks 0..255 h-half GEMM -> partial gates(+bias)
//       blocks 256..511 attention -> xi tiles, then signal g_prod[mslab]
//   k2: W prefetch (overlaps k1) -> poll g_prod -> xi-GEMM (overlaps k1's
//       h-GEMM!) -> griddep wait -> + partial -> fused LSTM update.
// (tcgen05 unavailable: harness PTX target is sm_103.)
// ---------------------------------------------------------------------------

#define BATCH 256
#define SEQ   128
#define IN    512
#define H     512
#define NG    2048
#define ATILE 8192                 // 64 rows x 128B (K=64 fp16)
#define BTILE 4096                 // 32 rows x 128B
#define DSM1  49152                // k1: W 32K + A 2x8K
#define DSM2  98304                // k2: W 32K + A 4x16K

__device__ unsigned char g_AT[4 * 16 * ATILE];     // [mblk][ktile] fp16
__device__ unsigned char g_WT[64 * 16 * BTILE];    // [nblk][ktile] fp16
__device__ float         g_bias[NG];
__device__ __half2       g_x16 [BATCH * SEQ * (IN/2)];
__device__ __half2       g_Wa16[SEQ * (IN/2)];
__device__ float         g_c   [BATCH * H];
__device__ float         g_gates[BATCH * NG];      // h-half partial (+bias)
__device__ unsigned      g_prod[4];                // xi ready counters per mslab
__device__ unsigned      g_done[4];                // consumer counters per mslab

__device__ __forceinline__ uint32_t swz(uint32_t o) { return o ^ ((o >> 3) & 0x70u); }
__device__ __forceinline__ float sigf(float x) { return 1.0f / (1.0f + expf(-x)); }

__device__ __forceinline__ uint32_t smem_u32(const void* p) {
    uint32_t a;
    asm("{ .reg .u64 t; cvta.to.shared.u64 t, %1; cvt.u32.u64 %0, t; }" : "=r"(a) : "l"(p));
    return a;
}
#define GRIDDEP_LAUNCH asm volatile("griddepcontrol.launch_dependents;" ::: "memory")
#define GRIDDEP_WAIT   asm volatile("griddepcontrol.wait;" ::: "memory")
#define FENCE_PROXY_ASYNC asm volatile("fence.proxy.async;" ::: "memory")
#define MBAR_INIT(a, n) asm volatile("mbarrier.init.shared.b64 [%0], %1;" :: "r"(a), "r"(n) : "memory")
#define MBAR_EXPECT_TX(a, b) asm volatile("mbarrier.arrive.expect_tx.shared.b64 _, [%0], %1;" :: "r"(a), "r"(b) : "memory")
#define MBAR_WAIT(a, par) do { \
    asm volatile("{ .reg .pred P; WL%=: mbarrier.try_wait.parity.acquire.cta.shared::cta.b64 P, [%0], %1, 0x989680; @P bra.uni WD%=; bra.uni WL%=; WD%=: }" \
                 :: "r"(a), "r"(par) : "memory"); } while (0)

__device__ __forceinline__ void bulk_g2s(uint32_t dst, const void* src, uint32_t bytes, uint32_t mbar) {
    asm volatile("cp.async.bulk.shared::cluster.global.mbarrier::complete_tx::bytes [%0], [%1], %2, [%3];"
                 :: "r"(dst), "l"(src), "r"(bytes), "r"(mbar) : "memory");
}

__device__ __forceinline__ void ldm_x4(uint32_t* r, const void* p) {
    uint32_t a = smem_u32(p);
    asm volatile("ldmatrix.sync.aligned.m8n8.x4.shared.b16 {%0,%1,%2,%3}, [%4];"
                 : "=r"(r[0]), "=r"(r[1]), "=r"(r[2]), "=r"(r[3]) : "r"(a));
}
__device__ __forceinline__ void mma16816(float* c, const uint32_t* a, uint32_t b0, uint32_t b1) {
    asm volatile(
        "mma.sync.aligned.m16n8k16.row.col.f32.f16.f16.f32 "
        "{%0,%1,%2,%3}, {%4,%5,%6,%7}, {%8,%9}, {%0,%1,%2,%3};"
        : "+f"(c[0]), "+f"(c[1]), "+f"(c[2]), "+f"(c[3])
        : "r"(a[0]), "r"(a[1]), "r"(a[2]), "r"(a[3]), "r"(b0), "r"(b1));
}

// ---------------- prep ---------------------------------------------------------
__global__ void prep_a(const float* __restrict__ W_ih, const float* __restrict__ W_hh,
                       const float* __restrict__ b_ih, const float* __restrict__ b_hh) {
    int i = blockIdx.x * blockDim.x + threadIdx.x;
    int n = i >> 10, kc = i & 1023;
    int j = (n & 3) * 512 + (n >> 2);
    float w = (kc < IN) ? W_ih[j * IN + kc] : W_hh[j * H + (kc - IN)];
    uint32_t off = (uint32_t)((n >> 5) * 16 + (kc >> 6)) * BTILE + swz((n & 31) * 128 + (kc & 63) * 2);
    *(__half*)(g_WT + off) = __float2half_rn(w);
    if (i < NG) {
        int jb = (i & 3) * 512 + (i >> 2);
        g_bias[i] = b_ih[jb] + b_hh[jb];
    }
}

__global__ void prep_b(const float* __restrict__ x, const float* __restrict__ Wa) {
    int blk = blockIdx.x, tid = threadIdx.x;
    if (blk < 8192) {
        size_t i = (size_t)blk * 1024 + tid;
        float2 v = ((const float2*)x)[i];
        g_x16[i] = __floats2half2_rn(v.x, v.y);
    } else if (blk < 8224) {
        int i = (blk - 8192) * 1024 + tid;
        float2 v = ((const float2*)Wa)[i];
        g_Wa16[i] = __floats2half2_rn(v.x, v.y);
    } else {
        int b = (blk - 8224) * 2 + (tid >> 9);
        int k = tid & 511;
        float gi = g_bias[k * 4 + 0], gg = g_bias[k * 4 + 2], go = g_bias[k * 4 + 3];
        float c0 = sigf(gi) * tanhf(gg);
        float h0 = sigf(go) * tanhf(c0);
        g_c[b * H + k] = c0;
        uint32_t off = (uint32_t)((b >> 6) * 16 + 8 + (k >> 6)) * ATILE + swz((b & 63) * 128 + (k & 63) * 2);
        *(__half*)(g_AT + off) = __float2half_rn(h0);
    }
}

// 32m x 16n over 2 kq (K=32)
__device__ __forceinline__ void c3216(const unsigned char* A, const unsigned char* B,
                                      int wm, int wn, int lane, int kq0, float acc[2][2][4]) {
    #pragma unroll
    for (int q = 0; q < 2; q++) {
        const int kb = (kq0 + q) * 16;
        uint32_t a0[4], a1[4], b0[4];
        const uint32_t kcol = (kb + (lane >> 4) * 8) * 2;
        ldm_x4(a0, A + swz((wm + (lane & 15)) * 128 + kcol));
        ldm_x4(a1, A + swz((wm + 16 + (lane & 15)) * 128 + kcol));
        const int br = wn + (lane & 7) + ((lane >> 4) << 3);
        ldm_x4(b0, B + swz(br * 128 + (kb + ((lane >> 3) & 1) * 8) * 2));
        mma16816(acc[0][0], a0, b0[0], b0[1]);
        mma16816(acc[0][1], a0, b0[2], b0[3]);
        mma16816(acc[1][0], a1, b0[0], b0[1]);
        mma16816(acc[1][1], a1, b0[2], b0[3]);
    }
}

// 32m x 32n over 2 kq (K=32)
__device__ __forceinline__ void c3232(const unsigned char* A, const unsigned char* B,
                                      int wm, int lane, int kq0, float acc[2][4][4]) {
    #pragma unroll
    for (int q = 0; q < 2; q++) {
        const int kb = (kq0 + q) * 16;
        uint32_t a0[4], a1[4], b0[4], b1[4];
        const uint32_t kcol = (kb + (lane >> 4) * 8) * 2;
        ldm_x4(a0, A + swz((wm + (lane & 15)) * 128 + kcol));
        ldm_x4(a1, A + swz((wm + 16 + (lane & 15)) * 128 + kcol));
        const int br = (lane & 7) + ((lane >> 4) << 3);
        const uint32_t bk = (kb + ((lane >> 3) & 1) * 8) * 2;
        ldm_x4(b0, B + swz(br * 128 + bk));
        ldm_x4(b1, B + swz((br + 16) * 128 + bk));
        mma16816(acc[0][0], a0, b0[0], b0[1]);
        mma16816(acc[0][1], a0, b0[2], b0[3]);
        mma16816(acc[0][2], a0, b1[0], b1[1]);
        mma16816(acc[0][3], a0, b1[2], b1[3]);
        mma16816(acc[1][0], a1, b0[0], b0[1]);
        mma16816(acc[1][1], a1, b0[2], b0[3]);
        mma16816(acc[1][2], a1, b1[0], b1[1]);
        mma16816(acc[1][3], a1, b1[2], b1[3]);
    }
}

// ---------------- k1 GEMM: h-half, W resident, A 8x8KB stages ------------------
__device__ __forceinline__ void gemm_k1(unsigned char* sm, int bidx) {
    __shared__ __align__(8) uint64_t wbar, abar[2];
    const int tid = threadIdx.x, lane = tid & 31, warp = tid >> 5;
    const int bn = bidx & 63, bm = bidx >> 6;
    const int wk = warp & 1, wm = ((warp >> 1) & 1) * 32, wn = (warp >> 2) * 16;

    if (tid == 0) {
        MBAR_INIT(smem_u32(&wbar), 1);
        MBAR_INIT(smem_u32(&abar[0]), 1);
        MBAR_INIT(smem_u32(&abar[1]), 1);
    }
    __syncthreads();

    if (tid == 0) {
        MBAR_EXPECT_TX(smem_u32(&wbar), 32768);
        bulk_g2s(smem_u32(sm), g_WT + (size_t)(bn * 16 + 8) * BTILE, 32768, smem_u32(&wbar));
    }
    GRIDDEP_WAIT;                                       // prev k2 complete (h tiles)

    const unsigned char* sA = g_AT + (size_t)(bm * 16 + 8) * ATILE;
    const uint32_t smA = smem_u32(sm) + 32768;
    if (tid == 0) {
        MBAR_EXPECT_TX(smem_u32(&abar[0]), 8192);
        bulk_g2s(smA, sA, 8192, smem_u32(&abar[0]));
        MBAR_EXPECT_TX(smem_u32(&abar[1]), 8192);
        bulk_g2s(smA + 8192, sA + ATILE, 8192, smem_u32(&abar[1]));
    }
    MBAR_WAIT(smem_u32(&wbar), 0);

    float acc[2][2][4] = {};
    for (int s = 0; s < 8; s++) {
        MBAR_WAIT(smem_u32(&abar[s & 1]), (s >> 1) & 1);
        c3216(sm + 32768 + (s & 1) * 8192, sm + s * BTILE, wm, wn, lane, wk * 2, acc);
        __syncthreads();
        if (tid == 0 && s + 2 < 8) {
            MBAR_EXPECT_TX(smem_u32(&abar[s & 1]), 8192);
            bulk_g2s(smA + (s & 1) * 8192, sA + (size_t)(s + 2) * ATILE, 8192, smem_u32(&abar[s & 1]));
        }
    }

    float* gsm = (float*)sm;                            // reuse W region: [2][64][36]
    float* gk = gsm + wk * 2304;
    #pragma unroll
    for (int mi = 0; mi < 2; mi++)
        #pragma unroll
        for (int ni = 0; ni < 2; ni++) {
            const int r = wm + mi * 16 + (lane >> 2);
            const int c = wn + ni * 8 + (lane & 3) * 2;
            gk[r * 36 + c]           = acc[mi][ni][0];
            gk[r * 36 + c + 1]       = acc[mi][ni][1];
            gk[(r + 8) * 36 + c]     = acc[mi][ni][2];
            gk[(r + 8) * 36 + c + 1] = acc[mi][ni][3];
        }
    __syncthreads();

    const int kl = tid & 7;
    const float4 bias = *(const float4*)&g_bias[bn * 32 + kl * 4];
    #pragma unroll
    for (int j = 0; j < 2; j++) {
        const int bl = (tid >> 3) + j * 32;
        float4 v0 = *(const float4*)&gsm[bl * 36 + kl * 4];
        float4 v1 = *(const float4*)&gsm[2304 + bl * 36 + kl * 4];
        float4 v = make_float4(v0.x + v1.x + bias.x, v0.y + v1.y + bias.y,
                               v0.z + v1.z + bias.z, v0.w + v1.w + bias.w);
        *(float4*)&g_gates[(size_t)(bm * 64 + bl) * NG + bn * 32 + kl * 4] = v;
    }
}

// ---------------- k2: W prefetch -> poll xi -> GEMM -> wait -> update ----------
__global__ void __launch_bounds__(256, 2) k2_xgemm_update(float* __restrict__ out, int t) {
    extern __shared__ unsigned char sm[];
    __shared__ __align__(8) uint64_t wbar, abar[4];
    GRIDDEP_LAUNCH;
    const int tid = threadIdx.x, lane = tid & 31, warp = tid >> 5;
    const int bn = blockIdx.x & 63, bm = blockIdx.x >> 6;
    const int wk = warp & 3, wm = (warp >> 2) * 32;

    if (tid == 0) {
        MBAR_INIT(smem_u32(&wbar), 1);
        #pragma unroll
        for (int i = 0; i < 4; i++) MBAR_INIT(smem_u32(&abar[i]), 1);
    }
    __syncthreads();

    // W slab prefetch (fully independent of k1)
    if (tid == 0) {
        MBAR_EXPECT_TX(smem_u32(&wbar), 32768);
        bulk_g2s(smem_u32(sm), g_WT + (size_t)(bn * 16) * BTILE, 32768, smem_u32(&wbar));
    }

    // xi handshake: wait for the 64 attention CTAs of this m-slab, then load A
    if (tid == 0) {
        while (*((volatile unsigned*)&g_prod[bm]) < 64u) __nanosleep(32);
        __threadfence();                                // acquire
        const unsigned char* sA = g_AT + (size_t)(bm * 16) * ATILE;
        #pragma unroll
        for (int s = 0; s < 4; s++) {
            MBAR_EXPECT_TX(smem_u32(&abar[s]), 16384);
            bulk_g2s(smem_u32(sm) + 32768 + s * 16384, sA + (size_t)s * 2 * ATILE, 16384,
                     smem_u32(&abar[s]));
        }
    }
    MBAR_WAIT(smem_u32(&wbar), 0);

    // xi-GEMM overlaps k1's h-GEMM
    float acc[2][4][4] = {};
    #pragma unroll
    for (int s = 0; s < 4; s++) {
        MBAR_WAIT(smem_u32(&abar[s]), 0);
        const unsigned char* A = sm + 32768 + s * 16384 + (wk & 1) * ATILE;
        const unsigned char* B = sm + (2 * s + (wk & 1)) * BTILE;
        c3232(A, B, wm, lane, (wk >> 1) * 2, acc);
    }

    GRIDDEP_WAIT;                                       // k1 h-GEMM complete
    const int kl = tid & 7;
    const int k  = bn * 8 + kl;
    const int bl0 = tid >> 3, bl1 = bl0 + 32;
    const int batch0 = bm * 64 + bl0, batch1 = bm * 64 + bl1;
    const float4 gp0 = *(const float4*)&g_gates[(size_t)batch0 * NG + bn * 32 + kl * 4];
    const float4 gp1 = *(const float4*)&g_gates[(size_t)batch1 * NG + bn * 32 + kl * 4];
    const float cold0 = g_c[batch0 * H + k];
    const float cold1 = g_c[batch1 * H + k];
    __syncthreads();                                    // all smem reads done

    float* gsm = (float*)sm;                            // [4][64][36]
    float* gk = gsm + wk * 2304;
    #pragma unroll
    for (int mi = 0; mi < 2; mi++)
        #pragma unroll
        for (int ni = 0; ni < 4; ni++) {
            const int r = wm + mi * 16 + (lane >> 2);
            const int c = ni * 8 + (lane & 3) * 2;
            gk[r * 36 + c]           = acc[mi][ni][0];
            gk[r * 36 + c + 1]       = acc[mi][ni][1];
            gk[(r + 8) * 36 + c]     = acc[mi][ni][2];
            gk[(r + 8) * 36 + c + 1] = acc[mi][ni][3];
        }
    __syncthreads();

    const uint32_t tbase = ((uint32_t)bm * 16 + 8 + (k >> 6)) * ATILE;
    {
        float4 s0 = *(const float4*)&gsm[bl0 * 36 + kl * 4];
        float4 s1 = *(const float4*)&gsm[2304 + bl0 * 36 + kl * 4];
        float4 s2 = *(const float4*)&gsm[4608 + bl0 * 36 + kl * 4];
        float4 s3 = *(const float4*)&gsm[6912 + bl0 * 36 + kl * 4];
        float gi = s0.x + s1.x + s2.x + s3.x + gp0.x;
        float gf = s0.y + s1.y + s2.y + s3.y + gp0.y;
        float gg = s0.z + s1.z + s2.z + s3.z + gp0.z;
        float go = s0.w + s1.w + s2.w + s3.w + gp0.w;
        float cn = sigf(gf) * cold0 + sigf(gi) * tanhf(gg);
        float h  = sigf(go) * tanhf(cn);
        g_c[batch0 * H + k] = cn;
        *(__half*)(g_AT + tbase + swz(bl0 * 128 + (k & 63) * 2)) = __float2half_rn(h);
        out[((size_t)batch0 * SEQ + t) * H + k] = h;
    }
    {
        float4 s0 = *(const float4*)&gsm[bl1 * 36 + kl * 4];
        float4 s1 = *(const float4*)&gsm[2304 + bl1 * 36 + kl * 4];
        float4 s2 = *(const float4*)&gsm[4608 + bl1 * 36 + kl * 4];
        float4 s3 = *(const float4*)&gsm[6912 + bl1 * 36 + kl * 4];
        float gi = s0.x + s1.x + s2.x + s3.x + gp1.x;
        float gf = s0.y + s1.y + s2.y + s3.y + gp1.y;
        float gg = s0.z + s1.z + s2.z + s3.z + gp1.z;
        float go = s0.w + s1.w + s2.w + s3.w + gp1.w;
        float cn = sigf(gf) * cold1 + sigf(gi) * tanhf(gg);
        float h  = sigf(go) * tanhf(cn);
        g_c[batch1 * H + k] = cn;
        *(__half*)(g_AT + tbase + swz(bl1 * 128 + (k & 63) * 2)) = __float2half_rn(h);
        out[((size_t)batch1 * SEQ + t) * H + k] = h;
    }

    // consumer counter; last CTA per m-slab resets both counters (replay-safe)
    __syncthreads();
    if (tid == 0) {
        unsigned d = atomicAdd(&g_done[bm], 1);
        if (d == 63u) {
            atomicExch(&g_prod[bm], 0u);
            atomicExch(&g_done[bm], 0u);
        }
    }
}

// ---------------- attention: 1 batch per block, 256 thr ------------------------
struct AttnS {
    float c_sm[IN];
    float logit[SEQ], attn[SEQ];
    float rmax[4], rsum[4];
    float xpart[4][IN];
};

__device__ __forceinline__ void attn_body(unsigned char* dyn, int b, const float* __restrict__ ba) {
    AttnS* s = (AttnS*)dyn;
    const int tid = threadIdx.x, lane = tid & 31, warp = tid >> 5;

    s->c_sm[tid]       = g_c[b * H + tid];
    s->c_sm[256 + tid] = g_c[b * H + 256 + tid];
    __syncthreads();

    float4 cf[4];
    #pragma unroll
    for (int j = 0; j < 4; j++) cf[j] = ((const float4*)s->c_sm)[j * 32 + lane];

    const uint2* wa = (const uint2*)g_Wa16;
    #pragma unroll 2
    for (int si = 0; si < 16; si++) {
        const int sq = warp * 16 + si;
        const uint2* wp = wa + sq * 128;
        float acc = 0.0f;
        #pragma unroll
        for (int j = 0; j < 4; j++) {
            uint2 v = wp[j * 32 + lane];
            float2 w0 = __half22float2(*(const __half2*)&v.x);
            float2 w1 = __half22float2(*(const __half2*)&v.y);
            acc += cf[j].x * w0.x + cf[j].y * w0.y + cf[j].z * w1.x + cf[j].w * w1.y;
        }
        #pragma unroll
        for (int off = 16; off > 0; off >>= 1) acc += __shfl_xor_sync(0xffffffffu, acc, off);
        if (lane == 0) s->logit[sq] = acc + ba[sq];
    }
    __syncthreads();

    if (tid < 128) {
        float l = s->logit[tid], m = l;
        #pragma unroll
        for (int off = 16; off > 0; off >>= 1) m = fmaxf(m, __shfl_xor_sync(0xffffffffu, m, off));
        if (lane == 0) s->rmax[tid >> 5] = m;
    }
    __syncthreads();
    if (tid < 128) {
        float m = fmaxf(fmaxf(s->rmax[0], s->rmax[1]), fmaxf(s->rmax[2], s->rmax[3]));
        float e = expf(s->logit[tid] - m);
        s->attn[tid] = e;
        #pragma unroll
        for (int off = 16; off > 0; off >>= 1) e += __shfl_xor_sync(0xffffffffu, e, off);
        if (lane == 0) s->rsum[tid >> 5] = e;
    }
    __syncthreads();
    const float inv = 1.0f / (s->rsum[0] + s->rsum[1] + s->rsum[2] + s->rsum[3]);

    {
        const int g = tid >> 6, cth = tid & 63;
        const uint4* xp = ((const uint4*)g_x16) + (size_t)b * SEQ * 64 + cth;
        float acc[8] = {};
        #pragma unroll 4
        for (int i = 0; i < 32; i++) {
            const int sq = g * 32 + i;
            const float a = s->attn[sq];
            uint4 v = xp[(size_t)sq * 64];
            float2 p0 = __half22float2(*(const __half2*)&v.x);
            float2 p1 = __half22float2(*(const __half2*)&v.y);
            float2 p2 = __half22float2(*(const __half2*)&v.z);
            float2 p3 = __half22float2(*(const __half2*)&v.w);
            acc[0] += a * p0.x; acc[1] += a * p0.y;
            acc[2] += a * p1.x; acc[3] += a * p1.y;
            acc[4] += a * p2.x; acc[5] += a * p2.y;
            acc[6] += a * p3.x; acc[7] += a * p3.y;
        }
        #pragma unroll
        for (int q = 0; q < 8; q++) s->xpart[g][cth * 8 + q] = acc[q];
    }
    __syncthreads();

    {
        const int d0 = tid * 2;
        float v0 = (s->xpart[0][d0]     + s->xpart[1][d0])     + (s->xpart[2][d0]     + s->xpart[3][d0]);
        float v1 = (s->xpart[0][d0 + 1] + s->xpart[1][d0 + 1]) + (s->xpart[2][d0 + 1] + s->xpart[3][d0 + 1]);
        v0 *= inv; v1 *= inv;
        uint32_t off = ((uint32_t)(b >> 6) * 16 + (d0 >> 6)) * ATILE + swz((b & 63) * 128 + (d0 & 63) * 2);
        *(__half2*)(g_AT + off) = __floats2half2_rn(v0, v1);
    }
}

// ---------------- k1: h-GEMM + attention (attn signals xi readiness) -----------
__global__ void __launch_bounds__(256, 4) k1_hgemm_attn(const float* __restrict__ ba) {
    extern __shared__ unsigned char dyn[];
    GRIDDEP_LAUNCH;
    if (blockIdx.x < 256) {
        gemm_k1(dyn, blockIdx.x);
    } else {
        GRIDDEP_WAIT;                                   // c/h from previous step
        const int b = blockIdx.x - 256;
        attn_body(dyn, b, ba);
        __syncthreads();
        if (threadIdx.x == 0) {
            FENCE_PROXY_ASYNC;                          // xi stores -> async proxy
            __threadfence();                            // release
            atomicAdd(&g_prod[b >> 6], 1u);
        }
    }
}

// ---------------- launcher -------------------------------------------------------
static inline void launch_pdl(const void* fn, dim3 g, dim3 b, size_t sh, void** args) {
    cudaLaunchConfig_t cfg = {};
    cfg.gridDim = g;
    cfg.blockDim = b;
    cfg.dynamicSmemBytes = sh;
    cfg.stream = 0;
    cudaLaunchAttribute at[1];
    at[0].id = cudaLaunchAttributeProgrammaticStreamSerialization;
    at[0].val.programmaticStreamSerializationAllowed = 1;
    cfg.attrs = at;
    cfg.numAttrs = 1;
    if (cudaLaunchKernelExC(&cfg, fn, args) != cudaSuccess) {
        (void)cudaGetLastError();
        cudaLaunchKernel(fn, g, b, args, sh, 0);
    }
}

extern "C" void kernel_launch(void* const* d_in, const int* in_sizes, int n_in,
                              void* d_out, int out_size) {
    const float* x    = (const float*)d_in[0];
    const float* W_ih = (const float*)d_in[1];
    const float* W_hh = (const float*)d_in[2];
    const float* b_ih = (const float*)d_in[3];
    const float* b_hh = (const float*)d_in[4];
    const float* Wa   = (const float*)d_in[5];
    const float* ba   = (const float*)d_in[6];
    float* out = (float*)d_out;

    cudaFuncSetAttribute(k1_hgemm_attn,   cudaFuncAttributeMaxDynamicSharedMemorySize, DSM1);
    cudaFuncSetAttribute(k2_xgemm_update, cudaFuncAttributeMaxDynamicSharedMemorySize, DSM2);

    prep_a<<<2048, 1024>>>(W_ih, W_hh, b_ih, b_hh);
    prep_b<<<8352, 1024>>>(x, Wa);

    for (int t = 0; t < SEQ; t++) {
        const float* ba_arg = ba;
        void* a1[] = { (void*)&ba_arg };
        launch_pdl((const void*)k1_hgemm_attn, dim3(512), dim3(256), DSM1, a1);
        float* out_arg = out;
        int t_arg = t;
        void* a2[] = { (void*)&out_arg, (void*)&t_arg };
        launch_pdl((const void*)k2_xgemm_update, dim3(256), dim3(256), DSM2, a2);
    }
}

// round 16
// speedup vs baseline: 1.3147x; 1.1270x over previous
#include <cuda_runtime.h>
#include <cuda_bf16.h>
#include <cuda_fp16.h>
#include <cstdint>

// ---------------------------------------------------------------------------
// LSTM with attention-weighted inputs.  B=256, SEQ=128, IN=H=512.
// Gate dim PERMUTED: column n = 4*k + gate.
// A=[xi|h] fp16 tiles; W fp16 tiles, pre-swizzled (SW128) in gmem.
// PDL (griddepcontrol): each step kernel prefetches its W slab into smem
// while the PREVIOUS kernel runs, then waits; A streams in fine stages.
//   k1: blocks 0..255 h-half GEMM -> partial gates(+bias); 256..511 attn+xi
//   k2: xi-half GEMM + partial -> fused LSTM update, h tiles out.
// Attention: ILP-batched logits reductions, no-max softmax (logits bounded).
// (tcgen05 unavailable: harness PTX target is sm_103.)
// ---------------------------------------------------------------------------

#define BATCH 256
#define SEQ   128
#define IN    512
#define H     512
#define NG    2048
#define ATILE 8192                 // 64 rows x 128B (K=64 fp16)
#define BTILE 4096                 // 32 rows x 128B
#define DSM1  49152                // k1: W 32K + A 2x8K
#define DSM2  98304                // k2: W 32K + A 4x16K

__device__ unsigned char g_AT[4 * 16 * ATILE];     // [mblk][ktile] fp16
__device__ unsigned char g_WT[64 * 16 * BTILE];    // [nblk][ktile] fp16
__device__ float         g_bias[NG];
__device__ __half2       g_x16 [BATCH * SEQ * (IN/2)];
__device__ __half2       g_Wa16[SEQ * (IN/2)];
__device__ float         g_c   [BATCH * H];
__device__ float         g_gates[BATCH * NG];      // h-half partial (+bias)

__device__ __forceinline__ uint32_t swz(uint32_t o) { return o ^ ((o >> 3) & 0x70u); }
__device__ __forceinline__ float sigf(float x) { return 1.0f / (1.0f + expf(-x)); }

__device__ __forceinline__ uint32_t smem_u32(const void* p) {
    uint32_t a;
    asm("{ .reg .u64 t; cvta.to.shared.u64 t, %1; cvt.u32.u64 %0, t; }" : "=r"(a) : "l"(p));
    return a;
}
#define GRIDDEP_LAUNCH asm volatile("griddepcontrol.launch_dependents;" ::: "memory")
#define GRIDDEP_WAIT   asm volatile("griddepcontrol.wait;" ::: "memory")
#define FENCE_PROXY_ASYNC asm volatile("fence.proxy.async;" ::: "memory")
#define MBAR_INIT(a, n) asm volatile("mbarrier.init.shared.b64 [%0], %1;" :: "r"(a), "r"(n) : "memory")
#define MBAR_EXPECT_TX(a, b) asm volatile("mbarrier.arrive.expect_tx.shared.b64 _, [%0], %1;" :: "r"(a), "r"(b) : "memory")
#define MBAR_WAIT(a, par) do { \
    asm volatile("{ .reg .pred P; WL%=: mbarrier.try_wait.parity.acquire.cta.shared::cta.b64 P, [%0], %1, 0x989680; @P bra.uni WD%=; bra.uni WL%=; WD%=: }" \
                 :: "r"(a), "r"(par) : "memory"); } while (0)

__device__ __forceinline__ void bulk_g2s(uint32_t dst, const void* src, uint32_t bytes, uint32_t mbar) {
    asm volatile("cp.async.bulk.shared::cluster.global.mbarrier::complete_tx::bytes [%0], [%1], %2, [%3];"
                 :: "r"(dst), "l"(src), "r"(bytes), "r"(mbar) : "memory");
}

__device__ __forceinline__ void ldm_x4(uint32_t* r, const void* p) {
    uint32_t a = smem_u32(p);
    asm volatile("ldmatrix.sync.aligned.m8n8.x4.shared.b16 {%0,%1,%2,%3}, [%4];"
                 : "=r"(r[0]), "=r"(r[1]), "=r"(r[2]), "=r"(r[3]) : "r"(a));
}
__device__ __forceinline__ void mma16816(float* c, const uint32_t* a, uint32_t b0, uint32_t b1) {
    asm volatile(
        "mma.sync.aligned.m16n8k16.row.col.f32.f16.f16.f32 "
        "{%0,%1,%2,%3}, {%4,%5,%6,%7}, {%8,%9}, {%0,%1,%2,%3};"
        : "+f"(c[0]), "+f"(c[1]), "+f"(c[2]), "+f"(c[3])
        : "r"(a[0]), "r"(a[1]), "r"(a[2]), "r"(a[3]), "r"(b0), "r"(b1));
}

// ---------------- prep ---------------------------------------------------------
__global__ void prep_a(const float* __restrict__ W_ih, const float* __restrict__ W_hh,
                       const float* __restrict__ b_ih, const float* __restrict__ b_hh) {
    int i = blockIdx.x * blockDim.x + threadIdx.x;
    int n = i >> 10, kc = i & 1023;
    int j = (n & 3) * 512 + (n >> 2);
    float w = (kc < IN) ? W_ih[j * IN + kc] : W_hh[j * H + (kc - IN)];
    uint32_t off = (uint32_t)((n >> 5) * 16 + (kc >> 6)) * BTILE + swz((n & 31) * 128 + (kc & 63) * 2);
    *(__half*)(g_WT + off) = __float2half_rn(w);
    if (i < NG) {
        int jb = (i & 3) * 512 + (i >> 2);
        g_bias[i] = b_ih[jb] + b_hh[jb];
    }
}

__global__ void prep_b(const float* __restrict__ x, const float* __restrict__ Wa) {
    int blk = blockIdx.x, tid = threadIdx.x;
    if (blk < 8192) {
        size_t i = (size_t)blk * 1024 + tid;
        float2 v = ((const float2*)x)[i];
        g_x16[i] = __floats2half2_rn(v.x, v.y);
    } else if (blk < 8224) {
        int i = (blk - 8192) * 1024 + tid;
        float2 v = ((const float2*)Wa)[i];
        g_Wa16[i] = __floats2half2_rn(v.x, v.y);
    } else {
        int b = (blk - 8224) * 2 + (tid >> 9);
        int k = tid & 511;
        float gi = g_bias[k * 4 + 0], gg = g_bias[k * 4 + 2], go = g_bias[k * 4 + 3];
        float c0 = sigf(gi) * tanhf(gg);
        float h0 = sigf(go) * tanhf(c0);
        g_c[b * H + k] = c0;
        uint32_t off = (uint32_t)((b >> 6) * 16 + 8 + (k >> 6)) * ATILE + swz((b & 63) * 128 + (k & 63) * 2);
        *(__half*)(g_AT + off) = __float2half_rn(h0);
    }
}

// 32m x 16n over 2 kq (K=32)
__device__ __forceinline__ void c3216(const unsigned char* A, const unsigned char* B,
                                      int wm, int wn, int lane, int kq0, float acc[2][2][4]) {
    #pragma unroll
    for (int q = 0; q < 2; q++) {
        const int kb = (kq0 + q) * 16;
        uint32_t a0[4], a1[4], b0[4];
        const uint32_t kcol = (kb + (lane >> 4) * 8) * 2;
        ldm_x4(a0, A + swz((wm + (lane & 15)) * 128 + kcol));
        ldm_x4(a1, A + swz((wm + 16 + (lane & 15)) * 128 + kcol));
        const int br = wn + (lane & 7) + ((lane >> 4) << 3);
        ldm_x4(b0, B + swz(br * 128 + (kb + ((lane >> 3) & 1) * 8) * 2));
        mma16816(acc[0][0], a0, b0[0], b0[1]);
        mma16816(acc[0][1], a0, b0[2], b0[3]);
        mma16816(acc[1][0], a1, b0[0], b0[1]);
        mma16816(acc[1][1], a1, b0[2], b0[3]);
    }
}

// 32m x 32n over 2 kq (K=32)
__device__ __forceinline__ void c3232(const unsigned char* A, const unsigned char* B,
                                      int wm, int lane, int kq0, float acc[2][4][4]) {
    #pragma unroll
    for (int q = 0; q < 2; q++) {
        const int kb = (kq0 + q) * 16;
        uint32_t a0[4], a1[4], b0[4], b1[4];
        const uint32_t kcol = (kb + (lane >> 4) * 8) * 2;
        ldm_x4(a0, A + swz((wm + (lane & 15)) * 128 + kcol));
        ldm_x4(a1, A + swz((wm + 16 + (lane & 15)) * 128 + kcol));
        const int br = (lane & 7) + ((lane >> 4) << 3);
        const uint32_t bk = (kb + ((lane >> 3) & 1) * 8) * 2;
        ldm_x4(b0, B + swz(br * 128 + bk));
        ldm_x4(b1, B + swz((br + 16) * 128 + bk));
        mma16816(acc[0][0], a0, b0[0], b0[1]);
        mma16816(acc[0][1], a0, b0[2], b0[3]);
        mma16816(acc[0][2], a0, b1[0], b1[1]);
        mma16816(acc[0][3], a0, b1[2], b1[3]);
        mma16816(acc[1][0], a1, b0[0], b0[1]);
        mma16816(acc[1][1], a1, b0[2], b0[3]);
        mma16816(acc[1][2], a1, b1[0], b1[1]);
        mma16816(acc[1][3], a1, b1[2], b1[3]);
    }
}

// ---------------- k1 GEMM: h-half, W resident, A 8x8KB stages ------------------
__device__ __forceinline__ void gemm_k1(unsigned char* sm, int bidx) {
    __shared__ __align__(8) uint64_t wbar, abar[2];
    const int tid = threadIdx.x, lane = tid & 31, warp = tid >> 5;
    const int bn = bidx & 63, bm = bidx >> 6;
    const int wk = warp & 1, wm = ((warp >> 1) & 1) * 32, wn = (warp >> 2) * 16;

    if (tid == 0) {
        MBAR_INIT(smem_u32(&wbar), 1);
        MBAR_INIT(smem_u32(&abar[0]), 1);
        MBAR_INIT(smem_u32(&abar[1]), 1);
    }
    __syncthreads();

    if (tid == 0) {
        MBAR_EXPECT_TX(smem_u32(&wbar), 32768);
        bulk_g2s(smem_u32(sm), g_WT + (size_t)(bn * 16 + 8) * BTILE, 32768, smem_u32(&wbar));
    }
    GRIDDEP_WAIT;                                       // prev k2 complete (h tiles)

    const unsigned char* sA = g_AT + (size_t)(bm * 16 + 8) * ATILE;
    const uint32_t smA = smem_u32(sm) + 32768;
    if (tid == 0) {
        MBAR_EXPECT_TX(smem_u32(&abar[0]), 8192);
        bulk_g2s(smA, sA, 8192, smem_u32(&abar[0]));
        MBAR_EXPECT_TX(smem_u32(&abar[1]), 8192);
        bulk_g2s(smA + 8192, sA + ATILE, 8192, smem_u32(&abar[1]));
    }
    MBAR_WAIT(smem_u32(&wbar), 0);

    float acc[2][2][4] = {};
    for (int s = 0; s < 8; s++) {
        MBAR_WAIT(smem_u32(&abar[s & 1]), (s >> 1) & 1);
        c3216(sm + 32768 + (s & 1) * 8192, sm + s * BTILE, wm, wn, lane, wk * 2, acc);
        __syncthreads();
        if (tid == 0 && s + 2 < 8) {
            MBAR_EXPECT_TX(smem_u32(&abar[s & 1]), 8192);
            bulk_g2s(smA + (s & 1) * 8192, sA + (size_t)(s + 2) * ATILE, 8192, smem_u32(&abar[s & 1]));
        }
    }

    float* gsm = (float*)sm;                            // reuse W region: [2][64][36]
    float* gk = gsm + wk * 2304;
    #pragma unroll
    for (int mi = 0; mi < 2; mi++)
        #pragma unroll
        for (int ni = 0; ni < 2; ni++) {
            const int r = wm + mi * 16 + (lane >> 2);
            const int c = wn + ni * 8 + (lane & 3) * 2;
            gk[r * 36 + c]           = acc[mi][ni][0];
            gk[r * 36 + c + 1]       = acc[mi][ni][1];
            gk[(r + 8) * 36 + c]     = acc[mi][ni][2];
            gk[(r + 8) * 36 + c + 1] = acc[mi][ni][3];
        }
    __syncthreads();

    const int kl = tid & 7;
    const float4 bias = *(const float4*)&g_bias[bn * 32 + kl * 4];
    #pragma unroll
    for (int j = 0; j < 2; j++) {
        const int bl = (tid >> 3) + j * 32;
        float4 v0 = *(const float4*)&gsm[bl * 36 + kl * 4];
        float4 v1 = *(const float4*)&gsm[2304 + bl * 36 + kl * 4];
        float4 v = make_float4(v0.x + v1.x + bias.x, v0.y + v1.y + bias.y,
                               v0.z + v1.z + bias.z, v0.w + v1.w + bias.w);
        *(float4*)&g_gates[(size_t)(bm * 64 + bl) * NG + bn * 32 + kl * 4] = v;
    }
}

// ---------------- k2: xi-half GEMM (4-way K-split) + fused update --------------
__global__ void __launch_bounds__(256, 2) k2_xgemm_update(float* __restrict__ out, int t) {
    extern __shared__ unsigned char sm[];
    __shared__ __align__(8) uint64_t wbar, abar[4];
    GRIDDEP_LAUNCH;
    const int tid = threadIdx.x, lane = tid & 31, warp = tid >> 5;
    const int bn = blockIdx.x & 63, bm = blockIdx.x >> 6;
    const int wk = warp & 3, wm = (warp >> 2) * 32;

    if (tid == 0) {
        MBAR_INIT(smem_u32(&wbar), 1);
        #pragma unroll
        for (int i = 0; i < 4; i++) MBAR_INIT(smem_u32(&abar[i]), 1);
    }
    __syncthreads();

    // prologue (overlaps k1): W slab
    if (tid == 0) {
        MBAR_EXPECT_TX(smem_u32(&wbar), 32768);
        bulk_g2s(smem_u32(sm), g_WT + (size_t)(bn * 16) * BTILE, 32768, smem_u32(&wbar));
    }
    GRIDDEP_WAIT;                                       // k1 complete

    const int kl = tid & 7;
    const int k  = bn * 8 + kl;
    const int bl0 = tid >> 3, bl1 = bl0 + 32;
    const int batch0 = bm * 64 + bl0, batch1 = bm * 64 + bl1;
    const float4 gp0 = *(const float4*)&g_gates[(size_t)batch0 * NG + bn * 32 + kl * 4];
    const float4 gp1 = *(const float4*)&g_gates[(size_t)batch1 * NG + bn * 32 + kl * 4];
    const float cold0 = g_c[batch0 * H + k];
    const float cold1 = g_c[batch1 * H + k];

    const unsigned char* sA = g_AT + (size_t)(bm * 16) * ATILE;
    if (tid == 0) {
        #pragma unroll
        for (int s = 0; s < 4; s++) {
            MBAR_EXPECT_TX(smem_u32(&abar[s]), 16384);
            bulk_g2s(smem_u32(sm) + 32768 + s * 16384, sA + (size_t)s * 2 * ATILE, 16384,
                     smem_u32(&abar[s]));
        }
    }
    MBAR_WAIT(smem_u32(&wbar), 0);

    float acc[2][4][4] = {};
    #pragma unroll
    for (int s = 0; s < 4; s++) {
        MBAR_WAIT(smem_u32(&abar[s]), 0);
        const unsigned char* A = sm + 32768 + s * 16384 + (wk & 1) * ATILE;
        const unsigned char* B = sm + (2 * s + (wk & 1)) * BTILE;
        c3232(A, B, wm, lane, (wk >> 1) * 2, acc);
    }
    __syncthreads();

    float* gsm = (float*)sm;                            // [4][64][36]
    float* gk = gsm + wk * 2304;
    #pragma unroll
    for (int mi = 0; mi < 2; mi++)
        #pragma unroll
        for (int ni = 0; ni < 4; ni++) {
            const int r = wm + mi * 16 + (lane >> 2);
            const int c = ni * 8 + (lane & 3) * 2;
            gk[r * 36 + c]           = acc[mi][ni][0];
            gk[r * 36 + c + 1]       = acc[mi][ni][1];
            gk[(r + 8) * 36 + c]     = acc[mi][ni][2];
            gk[(r + 8) * 36 + c + 1] = acc[mi][ni][3];
        }
    __syncthreads();

    const uint32_t tbase = ((uint32_t)bm * 16 + 8 + (k >> 6)) * ATILE;
    {
        float4 s0 = *(const float4*)&gsm[bl0 * 36 + kl * 4];
        float4 s1 = *(const float4*)&gsm[2304 + bl0 * 36 + kl * 4];
        float4 s2 = *(const float4*)&gsm[4608 + bl0 * 36 + kl * 4];
        float4 s3 = *(const float4*)&gsm[6912 + bl0 * 36 + kl * 4];
        float gi = s0.x + s1.x + s2.x + s3.x + gp0.x;
        float gf = s0.y + s1.y + s2.y + s3.y + gp0.y;
        float gg = s0.z + s1.z + s2.z + s3.z + gp0.z;
        float go = s0.w + s1.w + s2.w + s3.w + gp0.w;
        float cn = sigf(gf) * cold0 + sigf(gi) * tanhf(gg);
        float h  = sigf(go) * tanhf(cn);
        g_c[batch0 * H + k] = cn;
        *(__half*)(g_AT + tbase + swz(bl0 * 128 + (k & 63) * 2)) = __float2half_rn(h);
        out[((size_t)batch0 * SEQ + t) * H + k] = h;
    }
    {
        float4 s0 = *(const float4*)&gsm[bl1 * 36 + kl * 4];
        float4 s1 = *(const float4*)&gsm[2304 + bl1 * 36 + kl * 4];
        float4 s2 = *(const float4*)&gsm[4608 + bl1 * 36 + kl * 4];
        float4 s3 = *(const float4*)&gsm[6912 + bl1 * 36 + kl * 4];
        float gi = s0.x + s1.x + s2.x + s3.x + gp1.x;
        float gf = s0.y + s1.y + s2.y + s3.y + gp1.y;
        float gg = s0.z + s1.z + s2.z + s3.z + gp1.z;
        float go = s0.w + s1.w + s2.w + s3.w + gp1.w;
        float cn = sigf(gf) * cold1 + sigf(gi) * tanhf(gg);
        float h  = sigf(go) * tanhf(cn);
        g_c[batch1 * H + k] = cn;
        *(__half*)(g_AT + tbase + swz(bl1 * 128 + (k & 63) * 2)) = __float2half_rn(h);
        out[((size_t)batch1 * SEQ + t) * H + k] = h;
    }
}

// ---------------- attention: 1 batch per block, 256 thr ------------------------
// logits: 8 interleaved accumulators per warp -> ILP-overlapped shuffle trees.
// softmax WITHOUT max-subtraction: logits are bounded (|l| << 88), exp safe.
struct AttnS {
    float c_sm[IN];
    float logit[SEQ], attn[SEQ];
    float rsum[4];
    float xpart[4][IN];
};

__device__ __forceinline__ void attn_body(unsigned char* dyn, int b, const float* __restrict__ ba) {
    AttnS* s = (AttnS*)dyn;
    const int tid = threadIdx.x, lane = tid & 31, warp = tid >> 5;

    s->c_sm[tid]       = g_c[b * H + tid];
    s->c_sm[256 + tid] = g_c[b * H + 256 + tid];
    __syncthreads();

    float4 cf[4];
    #pragma unroll
    for (int j = 0; j < 4; j++) cf[j] = ((const float4*)s->c_sm)[j * 32 + lane];

    const uint2* wa = (const uint2*)g_Wa16;
    #pragma unroll
    for (int half = 0; half < 2; half++) {
        const int s0 = warp * 16 + half * 8;
        float acc[8];
        #pragma unroll
        for (int i = 0; i < 8; i++) acc[i] = 0.0f;
        #pragma unroll
        for (int i = 0; i < 8; i++) {
            const uint2* wp = wa + (s0 + i) * 128;
            #pragma unroll
            for (int j = 0; j < 4; j++) {
                uint2 v = wp[j * 32 + lane];
                float2 w0 = __half22float2(*(const __half2*)&v.x);
                float2 w1 = __half22float2(*(const __half2*)&v.y);
                acc[i] += cf[j].x * w0.x + cf[j].y * w0.y + cf[j].z * w1.x + cf[j].w * w1.y;
            }
        }
        #pragma unroll
        for (int off = 16; off > 0; off >>= 1)
            #pragma unroll
            for (int i = 0; i < 8; i++)
                acc[i] += __shfl_xor_sync(0xffffffffu, acc[i], off);
        if (lane == 0) {
            #pragma unroll
            for (int i = 0; i < 8; i++) s->logit[s0 + i] = acc[i] + ba[s0 + i];
        }
    }
    __syncthreads();

    if (tid < 128) {
        float e = expf(s->logit[tid]);
        s->attn[tid] = e;
        #pragma unroll
        for (int off = 16; off > 0; off >>= 1) e += __shfl_xor_sync(0xffffffffu, e, off);
        if (lane == 0) s->rsum[tid >> 5] = e;
    }
    __syncthreads();
    const float inv = 1.0f / (s->rsum[0] + s->rsum[1] + s->rsum[2] + s->rsum[3]);

    {
        const int g = tid >> 6, cth = tid & 63;
        const uint4* xp = ((const uint4*)g_x16) + (size_t)b * SEQ * 64 + cth;
        float acc[8] = {};
        #pragma unroll 8
        for (int i = 0; i < 32; i++) {
            const int sq = g * 32 + i;
            const float a = s->attn[sq];
            uint4 v = xp[(size_t)sq * 64];
            float2 p0 = __half22float2(*(const __half2*)&v.x);
            float2 p1 = __half22float2(*(const __half2*)&v.y);
            float2 p2 = __half22float2(*(const __half2*)&v.z);
            float2 p3 = __half22float2(*(const __half2*)&v.w);
            acc[0] += a * p0.x; acc[1] += a * p0.y;
            acc[2] += a * p1.x; acc[3] += a * p1.y;
            acc[4] += a * p2.x; acc[5] += a * p2.y;
            acc[6] += a * p3.x; acc[7] += a * p3.y;
        }
        #pragma unroll
        for (int q = 0; q < 8; q++) s->xpart[g][cth * 8 + q] = acc[q];
    }
    __syncthreads();

    {
        const int d0 = tid * 2;
        float v0 = (s->xpart[0][d0]     + s->xpart[1][d0])     + (s->xpart[2][d0]     + s->xpart[3][d0]);
        float v1 = (s->xpart[0][d0 + 1] + s->xpart[1][d0 + 1]) + (s->xpart[2][d0 + 1] + s->xpart[3][d0 + 1]);
        v0 *= inv; v1 *= inv;
        uint32_t off = ((uint32_t)(b >> 6) * 16 + (d0 >> 6)) * ATILE + swz((b & 63) * 128 + (d0 & 63) * 2);
        *(__half2*)(g_AT + off) = __floats2half2_rn(v0, v1);
    }
}

// ---------------- k1: h-GEMM + attention -----------------------------------------
__global__ void __launch_bounds__(256, 4) k1_hgemm_attn(const float* __restrict__ ba) {
    extern __shared__ unsigned char dyn[];
    GRIDDEP_LAUNCH;
    if (blockIdx.x < 256) {
        gemm_k1(dyn, blockIdx.x);
    } else {
        GRIDDEP_WAIT;                                   // c/h from previous step
        attn_body(dyn, blockIdx.x - 256, ba);
    }
}

// ---------------- launcher -------------------------------------------------------
static inline void launch_pdl(const void* fn, dim3 g, dim3 b, size_t sh, void** args) {
    cudaLaunchConfig_t cfg = {};
    cfg.gridDim = g;
    cfg.blockDim = b;
    cfg.dynamicSmemBytes = sh;
    cfg.stream = 0;
    cudaLaunchAttribute at[1];
    at[0].id = cudaLaunchAttributeProgrammaticStreamSerialization;
    at[0].val.programmaticStreamSerializationAllowed = 1;
    cfg.attrs = at;
    cfg.numAttrs = 1;
    if (cudaLaunchKernelExC(&cfg, fn, args) != cudaSuccess) {
        (void)cudaGetLastError();                       // clear; fall back to plain
        cudaLaunchKernel(fn, g, b, args, sh, 0);
    }
}

extern "C" void kernel_launch(void* const* d_in, const int* in_sizes, int n_in,
                              void* d_out, int out_size) {
    const float* x    = (const float*)d_in[0];
    const float* W_ih = (const float*)d_in[1];
    const float* W_hh = (const float*)d_in[2];
    const float* b_ih = (const float*)d_in[3];
    const float* b_hh = (const float*)d_in[4];
    const float* Wa   = (const float*)d_in[5];
    const float* ba   = (const float*)d_in[6];
    float* out = (float*)d_out;

    cudaFuncSetAttribute(k1_hgemm_attn,   cudaFuncAttributeMaxDynamicSharedMemorySize, DSM1);
    cudaFuncSetAttribute(k2_xgemm_update, cudaFuncAttributeMaxDynamicSharedMemorySize, DSM2);

    prep_a<<<2048, 1024>>>(W_ih, W_hh, b_ih, b_hh);
    prep_b<<<8352, 1024>>>(x, Wa);

    for (int t = 0; t < SEQ; t++) {
        const float* ba_arg = ba;
        void* a1[] = { (void*)&ba_arg };
        launch_pdl((const void*)k1_hgemm_attn, dim3(512), dim3(256), DSM1, a1);
        float* out_arg = out;
        int t_arg = t;
        void* a2[] = { (void*)&out_arg, (void*)&t_arg };
        launch_pdl((const void*)k2_xgemm_update, dim3(256), dim3(256), DSM2, a2);
    }
}